// round 1
// baseline (speedup 1.0000x reference)
#include <cuda_runtime.h>
#include <math.h>

#define T_STEPS 8192
#define HID     1024
#define IN_K    2048
#define NGATE   3072
#define NCTA    128

// ---- device scratch (allocation-free: __device__ globals) ----
__device__ float g_gi[(size_t)T_STEPS * NGATE];      // ~100.7 MB precomputed input gates
__device__ float g_hv[2][HID];                        // double-buffered h
__device__ volatile unsigned g_flag[NCTA];            // per-CTA epoch flags

// =====================================================================
// Kernel 1: gi = features @ w_ih[:, :2048]^T  + rewards * w_ih[:,2048] + b_ih
// fp32 SIMT tiled GEMM, BM=BN=128, BK=16, 8x8 per thread
// =====================================================================
#define BM 128
#define BN 128
#define BK 16

__global__ void __launch_bounds__(256) gi_gemm(
    const float* __restrict__ feat,   // [8192, 2048]
    const float* __restrict__ rew,    // [8192]
    const float* __restrict__ w_ih,   // [3072, 2049]  (row stride 2049!)
    const float* __restrict__ b_ih)   // [3072]
{
    __shared__ float As[BK][BM];
    __shared__ float Ws[BK][BN];

    const int tid   = threadIdx.x;
    const int nBase = blockIdx.x * BN;
    const int mBase = blockIdx.y * BM;
    const int tx = tid & 15;          // n direction
    const int ty = tid >> 4;          // m direction

    float acc[8][8];
    #pragma unroll
    for (int i = 0; i < 8; i++)
        #pragma unroll
        for (int j = 0; j < 8; j++) acc[i][j] = 0.f;

    for (int kB = 0; kB < IN_K; kB += BK) {
        // A tile: 512 float4 total, 2 per thread (features rows are 16B aligned)
        #pragma unroll
        for (int v = 0; v < 2; v++) {
            int f   = tid + v * 256;            // 0..511
            int row = f >> 2;
            int kq  = (f & 3) << 2;
            float4 a = *reinterpret_cast<const float4*>(
                &feat[(size_t)(mBase + row) * IN_K + kB + kq]);
            As[kq + 0][row] = a.x;
            As[kq + 1][row] = a.y;
            As[kq + 2][row] = a.z;
            As[kq + 3][row] = a.w;
        }
        // W tile: scalar loads (row stride 2049 floats -> not float4 aligned)
        #pragma unroll
        for (int v = 0; v < 8; v++) {
            int f   = tid + v * 256;            // 0..2047
            int row = f >> 4;
            int kk  = f & 15;
            Ws[kk][row] = w_ih[(size_t)(nBase + row) * 2049 + kB + kk];
        }
        __syncthreads();

        #pragma unroll
        for (int k = 0; k < BK; k++) {
            float a[8], b[8];
            // vectorized smem reads
            float4 a0 = *reinterpret_cast<const float4*>(&As[k][ty * 8 + 0]);
            float4 a1 = *reinterpret_cast<const float4*>(&As[k][ty * 8 + 4]);
            float4 b0 = *reinterpret_cast<const float4*>(&Ws[k][tx * 8 + 0]);
            float4 b1 = *reinterpret_cast<const float4*>(&Ws[k][tx * 8 + 4]);
            a[0]=a0.x; a[1]=a0.y; a[2]=a0.z; a[3]=a0.w;
            a[4]=a1.x; a[5]=a1.y; a[6]=a1.z; a[7]=a1.w;
            b[0]=b0.x; b[1]=b0.y; b[2]=b0.z; b[3]=b0.w;
            b[4]=b1.x; b[5]=b1.y; b[6]=b1.z; b[7]=b1.w;
            #pragma unroll
            for (int i = 0; i < 8; i++)
                #pragma unroll
                for (int j = 0; j < 8; j++)
                    acc[i][j] = fmaf(a[i], b[j], acc[i][j]);
        }
        __syncthreads();
    }

    // epilogue: + rewards[m]*w_ih[n][2048] + b_ih[n]
    float rw[8], wl[8], bb[8];
    #pragma unroll
    for (int i = 0; i < 8; i++) rw[i] = rew[mBase + ty * 8 + i];
    #pragma unroll
    for (int j = 0; j < 8; j++) {
        int n = nBase + tx * 8 + j;
        wl[j] = w_ih[(size_t)n * 2049 + 2048];
        bb[j] = b_ih[n];
    }
    #pragma unroll
    for (int i = 0; i < 8; i++) {
        int m = mBase + ty * 8 + i;
        #pragma unroll
        for (int j = 0; j < 8; j++) {
            int n = nBase + tx * 8 + j;
            g_gi[(size_t)m * NGATE + n] = acc[i][j] + rw[i] * wl[j] + bb[j];
        }
    }
}

// =====================================================================
// Kernel 2: reset epoch flags (graph replays reuse the device globals)
// =====================================================================
__global__ void init_flags()
{
    if (threadIdx.x < NCTA) g_flag[threadIdx.x] = 0u;
}

// =====================================================================
// Kernel 3: persistent GRU reverse scan.
// 128 CTAs x 256 threads. CTA c owns hidden units [8c, 8c+8).
// Warp w handles unit u = 8c + w; the 3 w_hh rows for u live in 96 regs/thread.
// Per step: CTA-level h broadcast through L2 with per-CTA epoch flags.
// =====================================================================
__device__ __forceinline__ float sigmoidf_(float x)
{
    return __fdividef(1.f, 1.f + __expf(-x));
}
__device__ __forceinline__ float tanhf_(float x)
{
    float ax = fabsf(x);
    float e  = __expf(-2.f * ax);
    float t  = __fdividef(1.f - e, 1.f + e);
    return copysignf(t, x);
}

__global__ void __launch_bounds__(256, 1) gru_scan(
    const float* __restrict__ w_hh,   // [3072, 1024]
    const float* __restrict__ b_hh,   // [3072]
    float* __restrict__ out)          // [1024]
{
    __shared__ float h_sm[HID];

    const int c = blockIdx.x;
    const int w = threadIdx.x >> 5;
    const int l = threadIdx.x & 31;
    const int u = c * 8 + w;

    // ---- register-resident recurrent weights: lane l holds k = l + 32j ----
    float wr[32], wz[32], wn[32];
    {
        const float* pr = w_hh + (size_t)(          u) * HID + l;
        const float* pz = w_hh + (size_t)(HID     + u) * HID + l;
        const float* pn = w_hh + (size_t)(2 * HID + u) * HID + l;
        #pragma unroll
        for (int j = 0; j < 32; j++) {
            wr[j] = pr[32 * j];
            wz[j] = pz[32 * j];
            wn[j] = pn[32 * j];
        }
    }
    const float bhr = b_hh[u];
    const float bhz = b_hh[HID + u];
    const float bhn = b_hh[2 * HID + u];

    // h^0 = 0
    {
        float4 z4 = make_float4(0.f, 0.f, 0.f, 0.f);
        *reinterpret_cast<float4*>(&h_sm[threadIdx.x * 4]) = z4;
    }
    float hval = 0.f;   // this warp's unit value (h_prev[u])

    for (int s = 0; s < T_STEPS; s++) {
        const int t = T_STEPS - 1 - s;   // reverse scan
        // prefetch gi for this step (independent of h -> issue before poll)
        const float* gip = g_gi + (size_t)t * NGATE + u;
        const float gir = __ldg(gip);
        const float giz = __ldg(gip + HID);
        const float gin = __ldg(gip + 2 * HID);

        if (s > 0) {
            if (w == 0) {
                // warp 0 polls all 128 epoch flags (4 coalesced lines)
                const unsigned target = (unsigned)s;
                for (;;) {
                    unsigned f0 = g_flag[l];
                    unsigned f1 = g_flag[l + 32];
                    unsigned f2 = g_flag[l + 64];
                    unsigned f3 = g_flag[l + 96];
                    unsigned fm = min(min(f0, f1), min(f2, f3));
                    if (__all_sync(0xffffffffu, fm >= target)) break;
                }
            }
        }
        __syncthreads();   // (A) flags observed -> safe to read h, h_sm free

        if (s > 0) {
            // cooperative fresh-h fetch (L2 only), 1 float4 per thread
            const float* vb = g_hv[s & 1];
            float4 hv4;
            hv4.x = __ldcg(vb + threadIdx.x * 4 + 0);
            hv4.y = __ldcg(vb + threadIdx.x * 4 + 1);
            hv4.z = __ldcg(vb + threadIdx.x * 4 + 2);
            hv4.w = __ldcg(vb + threadIdx.x * 4 + 3);
            *reinterpret_cast<float4*>(&h_sm[threadIdx.x * 4]) = hv4;
        }
        __syncthreads();   // (B) h staged in smem

        // three 1024-dot-products for unit u, split over 32 lanes
        float dr = 0.f, dz = 0.f, dn = 0.f;
        #pragma unroll
        for (int j = 0; j < 32; j++) {
            const float h = h_sm[l + 32 * j];
            dr = fmaf(wr[j], h, dr);
            dz = fmaf(wz[j], h, dz);
            dn = fmaf(wn[j], h, dn);
        }
        #pragma unroll
        for (int o = 16; o > 0; o >>= 1) {
            dr += __shfl_xor_sync(0xffffffffu, dr, o);
            dz += __shfl_xor_sync(0xffffffffu, dz, o);
            dn += __shfl_xor_sync(0xffffffffu, dn, o);
        }

        const float r = sigmoidf_(gir + dr + bhr);
        const float z = sigmoidf_(giz + dz + bhz);
        const float n = tanhf_(gin + r * (dn + bhn));
        hval = (1.f - z) * n + z * hval;

        if (s < T_STEPS - 1) {
            if (l == 0) {
                g_hv[(s + 1) & 1][u] = hval;
                __threadfence();          // data visible (GPU scope) before flag
            }
            __syncthreads();   // (C) all 8 units stored+fenced
            if (threadIdx.x == 0) g_flag[c] = (unsigned)(s + 1);
        }
    }

    if (l == 0) out[u] = hval;
}

// =====================================================================
extern "C" void kernel_launch(void* const* d_in, const int* in_sizes, int n_in,
                              void* d_out, int out_size)
{
    const float* feat = (const float*)d_in[0];   // [8192, 2048]
    const float* rew  = (const float*)d_in[1];   // [8192]
    const float* w_ih = (const float*)d_in[2];   // [3072, 2049]
    const float* w_hh = (const float*)d_in[3];   // [3072, 1024]
    const float* b_ih = (const float*)d_in[4];   // [3072]
    const float* b_hh = (const float*)d_in[5];   // [3072]
    float* out = (float*)d_out;                  // [1, 1024]

    dim3 ggrid(NGATE / BN, T_STEPS / BM);        // (24, 64)
    gi_gemm<<<ggrid, 256>>>(feat, rew, w_ih, b_ih);
    init_flags<<<1, 128>>>();
    gru_scan<<<NCTA, 256>>>(w_hh, b_hh, out);
}

// round 4
// speedup vs baseline: 1.0147x; 1.0147x over previous
#include <cuda_runtime.h>
#include <math.h>

#define T_STEPS 8192
#define HID     1024
#define IN_K    2048
#define NGATE   3072
#define NCTA    128

// ---- device scratch (allocation-free: __device__ globals) ----
__device__ float g_gi[(size_t)T_STEPS * NGATE];      // ~100.7 MB precomputed input gates
__device__ float g_hv[2][HID];                        // double-buffered h
__device__ volatile unsigned g_flag[NCTA];            // per-CTA epoch flags

// =====================================================================
// Kernel 1: gi = features @ w_ih[:, :2048]^T  + rewards * w_ih[:,2048] + b_ih
// fp32 SIMT tiled GEMM, BM=BN=128, BK=16, 8x8 per thread, 2 CTAs/SM
// =====================================================================
#define BM 128
#define BN 128
#define BK 16

__global__ void __launch_bounds__(256, 2) gi_gemm(
    const float* __restrict__ feat,   // [8192, 2048]
    const float* __restrict__ rew,    // [8192]
    const float* __restrict__ w_ih,   // [3072, 2049]  (row stride 2049!)
    const float* __restrict__ b_ih)   // [3072]
{
    __shared__ float As[BK][BM];
    __shared__ float Ws[BK][BN];

    const int tid   = threadIdx.x;
    const int nBase = blockIdx.x * BN;
    const int mBase = blockIdx.y * BM;
    const int tx = tid & 15;          // n direction
    const int ty = tid >> 4;          // m direction

    float acc[8][8];
    #pragma unroll
    for (int i = 0; i < 8; i++)
        #pragma unroll
        for (int j = 0; j < 8; j++) acc[i][j] = 0.f;

    for (int kB = 0; kB < IN_K; kB += BK) {
        // A tile: 512 float4 total, 2 per thread
        #pragma unroll
        for (int v = 0; v < 2; v++) {
            int f   = tid + v * 256;            // 0..511
            int row = f >> 2;
            int kq  = (f & 3) << 2;
            float4 a = *reinterpret_cast<const float4*>(
                &feat[(size_t)(mBase + row) * IN_K + kB + kq]);
            As[kq + 0][row] = a.x;
            As[kq + 1][row] = a.y;
            As[kq + 2][row] = a.z;
            As[kq + 3][row] = a.w;
        }
        // W tile: scalar loads (row stride 2049 floats -> not float4 aligned)
        #pragma unroll
        for (int v = 0; v < 8; v++) {
            int f   = tid + v * 256;            // 0..2047
            int row = f >> 4;
            int kk  = f & 15;
            Ws[kk][row] = w_ih[(size_t)(nBase + row) * 2049 + kB + kk];
        }
        __syncthreads();

        #pragma unroll
        for (int k = 0; k < BK; k++) {
            float a[8], b[8];
            float4 a0 = *reinterpret_cast<const float4*>(&As[k][ty * 8 + 0]);
            float4 a1 = *reinterpret_cast<const float4*>(&As[k][ty * 8 + 4]);
            float4 b0 = *reinterpret_cast<const float4*>(&Ws[k][tx * 8 + 0]);
            float4 b1 = *reinterpret_cast<const float4*>(&Ws[k][tx * 8 + 4]);
            a[0]=a0.x; a[1]=a0.y; a[2]=a0.z; a[3]=a0.w;
            a[4]=a1.x; a[5]=a1.y; a[6]=a1.z; a[7]=a1.w;
            b[0]=b0.x; b[1]=b0.y; b[2]=b0.z; b[3]=b0.w;
            b[4]=b1.x; b[5]=b1.y; b[6]=b1.z; b[7]=b1.w;
            #pragma unroll
            for (int i = 0; i < 8; i++)
                #pragma unroll
                for (int j = 0; j < 8; j++)
                    acc[i][j] = fmaf(a[i], b[j], acc[i][j]);
        }
        __syncthreads();
    }

    // epilogue: + rewards[m]*w_ih[n][2048] + b_ih[n]
    float rw[8], wl[8], bb[8];
    #pragma unroll
    for (int i = 0; i < 8; i++) rw[i] = rew[mBase + ty * 8 + i];
    #pragma unroll
    for (int j = 0; j < 8; j++) {
        int n = nBase + tx * 8 + j;
        wl[j] = w_ih[(size_t)n * 2049 + 2048];
        bb[j] = b_ih[n];
    }
    #pragma unroll
    for (int i = 0; i < 8; i++) {
        int m = mBase + ty * 8 + i;
        #pragma unroll
        for (int j = 0; j < 8; j++) {
            int n = nBase + tx * 8 + j;
            g_gi[(size_t)m * NGATE + n] = acc[i][j] + rw[i] * wl[j] + bb[j];
        }
    }
}

// =====================================================================
// Kernel 2: reset epoch flags (graph replays reuse the device globals)
// =====================================================================
__global__ void init_flags()
{
    if (threadIdx.x < NCTA) g_flag[threadIdx.x] = 0u;
}

// =====================================================================
// Kernel 3: persistent GRU reverse scan (R1 protocol, verified correct).
// 128 CTAs x 256 threads. CTA c owns units [8c, 8c+8); warp w -> unit u.
// Only change vs R1: __nanosleep backoff in the flag poll loop to stop
// same-address strong-load serialization at the LTS from starving the
// producer's flag store.
// =====================================================================
__device__ __forceinline__ float sigmoidf_(float x)
{
    return __fdividef(1.f, 1.f + __expf(-x));
}
__device__ __forceinline__ float tanhf_(float x)
{
    float ax = fabsf(x);
    float e  = __expf(-2.f * ax);
    float t  = __fdividef(1.f - e, 1.f + e);
    return copysignf(t, x);
}

__global__ void __launch_bounds__(256, 1) gru_scan(
    const float* __restrict__ w_hh,   // [3072, 1024]
    const float* __restrict__ b_hh,   // [3072]
    float* __restrict__ out)          // [1024]
{
    __shared__ float h_sm[HID];

    const int c = blockIdx.x;
    const int w = threadIdx.x >> 5;
    const int l = threadIdx.x & 31;
    const int u = c * 8 + w;

    // ---- register-resident recurrent weights: lane l holds k = l + 32j ----
    float wr[32], wz[32], wn[32];
    {
        const float* pr = w_hh + (size_t)(          u) * HID + l;
        const float* pz = w_hh + (size_t)(HID     + u) * HID + l;
        const float* pn = w_hh + (size_t)(2 * HID + u) * HID + l;
        #pragma unroll
        for (int j = 0; j < 32; j++) {
            wr[j] = pr[32 * j];
            wz[j] = pz[32 * j];
            wn[j] = pn[32 * j];
        }
    }
    const float bhr = b_hh[u];
    const float bhz = b_hh[HID + u];
    const float bhn = b_hh[2 * HID + u];

    // h^0 = 0
    {
        float4 z4 = make_float4(0.f, 0.f, 0.f, 0.f);
        *reinterpret_cast<float4*>(&h_sm[threadIdx.x * 4]) = z4;
    }
    float hval = 0.f;   // this warp's unit value (h_prev[u])

    for (int s = 0; s < T_STEPS; s++) {
        const int t = T_STEPS - 1 - s;   // reverse scan
        // prefetch gi for this step (independent of h -> issue before poll)
        const float* gip = g_gi + (size_t)t * NGATE + u;
        const float gir = __ldg(gip);
        const float giz = __ldg(gip + HID);
        const float gin = __ldg(gip + 2 * HID);

        if (s > 0) {
            if (w == 0) {
                // warp 0 polls all 128 epoch flags (4 coalesced lines),
                // with backoff so pollers don't starve the flag stores
                const unsigned target = (unsigned)s;
                for (;;) {
                    unsigned f0 = g_flag[l];
                    unsigned f1 = g_flag[l + 32];
                    unsigned f2 = g_flag[l + 64];
                    unsigned f3 = g_flag[l + 96];
                    unsigned fm = min(min(f0, f1), min(f2, f3));
                    if (__all_sync(0xffffffffu, fm >= target)) break;
                    __nanosleep(128);
                }
            }
        }
        __syncthreads();   // (A) flags observed -> safe to read h, h_sm free

        if (s > 0) {
            // cooperative fresh-h fetch (L2 only), 1 float4 per thread
            const float* vb = g_hv[s & 1];
            float4 hv4;
            hv4.x = __ldcg(vb + threadIdx.x * 4 + 0);
            hv4.y = __ldcg(vb + threadIdx.x * 4 + 1);
            hv4.z = __ldcg(vb + threadIdx.x * 4 + 2);
            hv4.w = __ldcg(vb + threadIdx.x * 4 + 3);
            *reinterpret_cast<float4*>(&h_sm[threadIdx.x * 4]) = hv4;
        }
        __syncthreads();   // (B) h staged in smem

        // three 1024-dot-products for unit u, split over 32 lanes
        float dr = 0.f, dz = 0.f, dn = 0.f;
        #pragma unroll
        for (int j = 0; j < 32; j++) {
            const float h = h_sm[l + 32 * j];
            dr = fmaf(wr[j], h, dr);
            dz = fmaf(wz[j], h, dz);
            dn = fmaf(wn[j], h, dn);
        }
        #pragma unroll
        for (int o = 16; o > 0; o >>= 1) {
            dr += __shfl_xor_sync(0xffffffffu, dr, o);
            dz += __shfl_xor_sync(0xffffffffu, dz, o);
            dn += __shfl_xor_sync(0xffffffffu, dn, o);
        }

        const float r = sigmoidf_(gir + dr + bhr);
        const float z = sigmoidf_(giz + dz + bhz);
        const float n = tanhf_(gin + r * (dn + bhn));
        hval = (1.f - z) * n + z * hval;

        if (s < T_STEPS - 1) {
            if (l == 0) {
                g_hv[(s + 1) & 1][u] = hval;
                __threadfence();          // data visible (GPU scope) before flag
            }
            __syncthreads();   // (C) all 8 units stored+fenced
            if (threadIdx.x == 0) g_flag[c] = (unsigned)(s + 1);
        }
    }

    if (l == 0) out[u] = hval;
}

// =====================================================================
extern "C" void kernel_launch(void* const* d_in, const int* in_sizes, int n_in,
                              void* d_out, int out_size)
{
    const float* feat = (const float*)d_in[0];   // [8192, 2048]
    const float* rew  = (const float*)d_in[1];   // [8192]
    const float* w_ih = (const float*)d_in[2];   // [3072, 2049]
    const float* w_hh = (const float*)d_in[3];   // [3072, 1024]
    const float* b_ih = (const float*)d_in[4];   // [3072]
    const float* b_hh = (const float*)d_in[5];   // [3072]
    float* out = (float*)d_out;                  // [1, 1024]

    dim3 ggrid(NGATE / BN, T_STEPS / BM);        // (24, 64)
    gi_gemm<<<ggrid, 256>>>(feat, rew, w_ih, b_ih);
    init_flags<<<1, 128>>>();
    gru_scan<<<NCTA, 256>>>(w_hh, b_hh, out);
}